// round 14
// baseline (speedup 1.0000x reference)
#include <cuda_runtime.h>
#include <cuda_fp16.h>
#include <math.h>
#include <stdint.h>

// Problem constants
#define B_      2
#define S_      2048
#define DMODEL  2048
#define NQH     32
#define NKVH    8
#define HD      64
#define KVDIM   (NKVH * HD)   // 512
#define KVD2    (2 * KVDIM)   // 1024 (K and V fused)
#define MROWS   (B_ * S_)     // 4096
#define NQW     (DMODEL * DMODEL)
#define NKW     (KVDIM * DMODEL)
#define NQKV    (DMODEL + KVD2)     // 3072 fused output cols

// ---------------------------------------------------------------------------
// Scratch (__device__ globals)
// g_W rows: [Wq(2048) | Wk(512) | Wv(512) | Wo(2048)] x K=2048, fp16 hi-only
// ---------------------------------------------------------------------------
__device__ __half g_W  [2 * NQW + 2 * NKW];
__device__ __half g_Xh [MROWS * DMODEL], g_Xl [MROWS * DMODEL];
__device__ __half g_Qh [MROWS * DMODEL], g_Ql [MROWS * DMODEL];
__device__ __half g_KVh[MROWS * KVD2];
__device__ __half g_AOh[MROWS * DMODEL], g_AOl[MROWS * DMODEL];

// ---------------------------------------------------------------------------
// helpers
// ---------------------------------------------------------------------------
__device__ __forceinline__ uint32_t smem_u32(const void* p) {
    return (uint32_t)__cvta_generic_to_shared(p);
}

__device__ __forceinline__ uint32_t packsplit_h(float a, float b, uint32_t& lo) {
    __half ha = __float2half_rn(a), hb = __float2half_rn(b);
    __half la = __float2half_rn(a - __half2float(ha));
    __half lb = __float2half_rn(b - __half2float(hb));
    lo = ((uint32_t)__half_as_ushort(lb) << 16) | (uint32_t)__half_as_ushort(la);
    return ((uint32_t)__half_as_ushort(hb) << 16) | (uint32_t)__half_as_ushort(ha);
}

__device__ __forceinline__ float fexp2(float x) {
    float r;
    asm("ex2.approx.f32 %0, %1;" : "=f"(r) : "f"(x));
    return r;
}

__device__ __forceinline__ void mma2(float* c, const uint32_t* a, uint32_t b0, uint32_t b1) {
    asm volatile(
        "mma.sync.aligned.m16n8k16.row.col.f32.f16.f16.f32 "
        "{%0,%1,%2,%3}, {%4,%5,%6,%7}, {%8,%9}, {%0,%1,%2,%3};"
        : "+f"(c[0]), "+f"(c[1]), "+f"(c[2]), "+f"(c[3])
        : "r"(a[0]), "r"(a[1]), "r"(a[2]), "r"(a[3]), "r"(b0), "r"(b1));
}

__device__ __forceinline__ void ldsm_x4(uint32_t* r, uint32_t addr) {
    asm volatile("ldmatrix.sync.aligned.m8n8.x4.shared.b16 {%0,%1,%2,%3}, [%4];"
                 : "=r"(r[0]), "=r"(r[1]), "=r"(r[2]), "=r"(r[3]) : "r"(addr));
}
__device__ __forceinline__ void ldsm_x4_t(uint32_t* r, uint32_t addr) {
    asm volatile("ldmatrix.sync.aligned.m8n8.x4.trans.shared.b16 {%0,%1,%2,%3}, [%4];"
                 : "=r"(r[0]), "=r"(r[1]), "=r"(r[2]), "=r"(r[3]) : "r"(addr));
}

#define SW(a) ((a) ^ (((a) >> 3) & 0x70))

__device__ __forceinline__ void cp16(uint32_t d, const void* s) {
    asm volatile("cp.async.cg.shared.global [%0], [%1], 16;\n" :: "r"(d), "l"(s));
}

#define QSCALE 0.18033688011112042f   // 1/sqrt(64) * log2(e)

// ---------------------------------------------------------------------------
// Weight convert (hi-only fp16) into packed g_W
// ---------------------------------------------------------------------------
__global__ void cvt_w4(const float* __restrict__ wq, const float* __restrict__ wk,
                       const float* __restrict__ wv, const float* __restrict__ wo,
                       __half* __restrict__ W)
{
    const int total2 = (2 * NQW + 2 * NKW) / 2;
    for (int i = blockIdx.x * blockDim.x + threadIdx.x; i < total2;
         i += gridDim.x * blockDim.x) {
        const int idx = i * 2;
        const float* src; int off;
        if (idx < NQW)                 { src = wq; off = idx; }
        else if (idx < NQW + NKW)      { src = wk; off = idx - NQW; }
        else if (idx < NQW + 2 * NKW)  { src = wv; off = idx - NQW - NKW; }
        else                           { src = wo; off = idx - NQW - 2 * NKW; }
        float2 v = *(const float2*)(src + off);
        __half2 h; h.x = __float2half_rn(v.x); h.y = __float2half_rn(v.y);
        *(__half2*)(W + idx) = h;
    }
}

// ---------------------------------------------------------------------------
// X: fp32 -> (hi, lo) fp16 buffers.
// ---------------------------------------------------------------------------
__global__ void split2_f16(const float* __restrict__ X,
                           __half* __restrict__ Yh, __half* __restrict__ Yl, int total4)
{
    for (int i = blockIdx.x * blockDim.x + threadIdx.x; i < total4;
         i += gridDim.x * blockDim.x) {
        const int idx = i * 4;
        float4 x = *(const float4*)(X + idx);
        uint32_t lo0, lo1;
        uint32_t hi0 = packsplit_h(x.x, x.y, lo0);
        uint32_t hi1 = packsplit_h(x.z, x.w, lo1);
        *(uint2*)(Yh + idx) = make_uint2(hi0, hi1);
        *(uint2*)(Yl + idx) = make_uint2(lo0, lo1);
    }
}

// ---------------------------------------------------------------------------
// Split-precision GEMM, CTA 128x128, 256 threads, 8 warps (4M x 2N),
// warp tile 32x64, TCK=64, 2-stage, 48KB/stage -> 2 CTAs/SM.
//   acc = (Ah+Al) * Bh^T
// Epilogue modes:
//   C != 0            : fp32 out, stride DMODEL
//   C == 0, gc < 2048 : Q out — 2-term fp16 (Qhi/Qlo), scaled by QSCALE
//   C == 0, gc >= 2048: KV out — 1-term fp16 (KVhi), stride KVD2
// ---------------------------------------------------------------------------
#define TCM 128
#define TCN 128
#define TCK 64
#define GA_AL 16384
#define GA_BH 32768
#define STAGE_BYTES 49152
#define GEMM_SMEM (2 * STAGE_BYTES)    // 98304

__global__ void __launch_bounds__(256, 2) gemm_split(
    const __half* __restrict__ Ah, const __half* __restrict__ Al,
    const __half* __restrict__ Bh,
    float* __restrict__ C,
    __half* __restrict__ Qhi, __half* __restrict__ Qlo,
    __half* __restrict__ KVhi,
    int M, int Kk)
{
    extern __shared__ __align__(1024) char sm[];
    const uint32_t sb = smem_u32(sm);

    const int tid  = threadIdx.x;
    const int lane = tid & 31;
    const int w    = tid >> 5;          // 0..7
    const int wm   = (w & 3) * 32;      // 4 M slabs of 32
    const int wn   = (w >> 2) * 64;     // 2 N slabs of 64
    const int bm   = blockIdx.y * TCM;
    const int bn   = blockIdx.x * TCN;

    float acc[2][8][4];
    #pragma unroll
    for (int mi = 0; mi < 2; mi++)
        #pragma unroll
        for (int nt = 0; nt < 8; nt++)
            #pragma unroll
            for (int r = 0; r < 4; r++) acc[mi][nt][r] = 0.0f;

    // load mapping (256 threads, 128 rows x 8 chunks of 16B per matrix):
    // thread t -> row t>>1, chunks (t&1)*4 + {0..3}
    const int lrow = tid >> 1, lch = (tid & 1) * 4;
    const __half* gAh = Ah + (size_t)(bm + lrow) * Kk + lch * 8;
    const __half* gAl = Al + (size_t)(bm + lrow) * Kk + lch * 8;
    const __half* gBh = Bh + (size_t)(bn + lrow) * Kk + lch * 8;

    auto load_stage = [&](int buf, int kt) {
        const uint32_t st = sb + buf * STAGE_BYTES;
        const int k0 = kt * TCK;
        #pragma unroll
        for (int j = 0; j < 4; j++) {
            const uint32_t d = SW((uint32_t)(lrow * 128 + (lch + j) * 16));
            cp16(st + d, gAh + k0 + j * 8);
            cp16(st + GA_AL + d, gAl + k0 + j * 8);
            cp16(st + GA_BH + d, gBh + k0 + j * 8);
        }
    };

    const int NT = Kk / TCK;
    load_stage(0, 0);
    asm volatile("cp.async.commit_group;\n");

    const int l15 = lane & 15;
    const int colh = (lane >> 4) << 4;

    for (int kt = 0; kt < NT; kt++) {
        const int cur = kt & 1;
        if (kt + 1 < NT) {
            load_stage(1 - cur, kt + 1);
            asm volatile("cp.async.commit_group;\n");
            asm volatile("cp.async.wait_group 1;\n");
        } else {
            asm volatile("cp.async.wait_group 0;\n");
        }
        __syncthreads();

        const uint32_t st = sb + cur * STAGE_BYTES;

        #pragma unroll
        for (int kk = 0; kk < 4; kk++) {
            const uint32_t colb = (uint32_t)(kk * 32 + colh);
            uint32_t ah[2][4], al[2][4];
            #pragma unroll
            for (int mi = 0; mi < 2; mi++) {
                const uint32_t off = SW((uint32_t)((wm + mi * 16 + l15) * 128) + colb);
                ldsm_x4(ah[mi], st + off);
                ldsm_x4(al[mi], st + GA_AL + off);
            }
            #pragma unroll
            for (int np = 0; np < 4; np++) {
                const uint32_t offb = SW((uint32_t)((wn + np * 16 + l15) * 128) + colb);
                uint32_t t[4];
                ldsm_x4(t, st + GA_BH + offb);
                mma2(acc[0][2*np],   ah[0], t[0], t[2]);
                mma2(acc[0][2*np+1], ah[0], t[1], t[3]);
                mma2(acc[1][2*np],   ah[1], t[0], t[2]);
                mma2(acc[1][2*np+1], ah[1], t[1], t[3]);
                mma2(acc[0][2*np],   al[0], t[0], t[2]);
                mma2(acc[0][2*np+1], al[0], t[1], t[3]);
                mma2(acc[1][2*np],   al[1], t[0], t[2]);
                mma2(acc[1][2*np+1], al[1], t[1], t[3]);
            }
        }
        __syncthreads();
    }

    // ---- epilogue (branch is CTA-uniform: bn either all-Q or all-KV)
    if (C) {
        #pragma unroll
        for (int mi = 0; mi < 2; mi++) {
            const int r0 = bm + wm + mi * 16 + (lane >> 2);
            #pragma unroll
            for (int nt = 0; nt < 8; nt++) {
                const int c0 = bn + wn + nt * 8 + 2 * (lane & 3);
                *(float2*)(C + (size_t)r0 * DMODEL + c0)       = make_float2(acc[mi][nt][0], acc[mi][nt][1]);
                *(float2*)(C + (size_t)(r0 + 8) * DMODEL + c0) = make_float2(acc[mi][nt][2], acc[mi][nt][3]);
            }
        }
    } else if (bn < DMODEL) {
        #pragma unroll
        for (int mi = 0; mi < 2; mi++) {
            const int r0 = bm + wm + mi * 16 + (lane >> 2);
            #pragma unroll
            for (int nt = 0; nt < 8; nt++) {
                const int c0 = bn + wn + nt * 8 + 2 * (lane & 3);
                uint32_t lo0, lo1;
                uint32_t hi0 = packsplit_h(acc[mi][nt][0] * QSCALE, acc[mi][nt][1] * QSCALE, lo0);
                uint32_t hi1 = packsplit_h(acc[mi][nt][2] * QSCALE, acc[mi][nt][3] * QSCALE, lo1);
                *(uint32_t*)(Qhi + (size_t)r0 * DMODEL + c0)       = hi0;
                *(uint32_t*)(Qlo + (size_t)r0 * DMODEL + c0)       = lo0;
                *(uint32_t*)(Qhi + (size_t)(r0 + 8) * DMODEL + c0) = hi1;
                *(uint32_t*)(Qlo + (size_t)(r0 + 8) * DMODEL + c0) = lo1;
            }
        }
    } else {
        #pragma unroll
        for (int mi = 0; mi < 2; mi++) {
            const int r0 = bm + wm + mi * 16 + (lane >> 2);
            #pragma unroll
            for (int nt = 0; nt < 8; nt++) {
                const int c0 = bn - DMODEL + wn + nt * 8 + 2 * (lane & 3);
                __half2 h0, h1;
                h0.x = __float2half_rn(acc[mi][nt][0]); h0.y = __float2half_rn(acc[mi][nt][1]);
                h1.x = __float2half_rn(acc[mi][nt][2]); h1.y = __float2half_rn(acc[mi][nt][3]);
                *(__half2*)(KVhi + (size_t)r0 * KVD2 + c0)       = h0;
                *(__half2*)(KVhi + (size_t)(r0 + 8) * KVD2 + c0) = h1;
            }
        }
    }
}

// ---------------------------------------------------------------------------
// fp16 flash attention (unchanged from round 13).
// ---------------------------------------------------------------------------
#define ATT_TILE_BYTES 8192
#define ATT_BUF_BYTES  (2 * ATT_TILE_BYTES)
#define ATT_SMEM       (2 * ATT_BUF_BYTES)   // 32768

__global__ void __launch_bounds__(256) flash_attn_mma(
    const __half* __restrict__ Qh, const __half* __restrict__ Ql,
    const __half* __restrict__ KVh,
    __half* __restrict__ AOh, __half* __restrict__ AOl)
{
    extern __shared__ __half smem[];
    const uint32_t sbase = smem_u32(smem);

    const int b    = blockIdx.z;
    const int h    = blockIdx.y;
    const int kvh  = h >> 2;
    const int tid  = threadIdx.x;
    const int lane = tid & 31;
    const int w    = tid >> 5;
    const int qrow = blockIdx.x * 128 + w * 16;

    uint32_t qf[2][4][4];
    {
        const size_t base = ((size_t)(b * S_ + qrow + (lane >> 2))) * DMODEL + h * HD + (lane & 3) * 2;
        #pragma unroll
        for (int kt = 0; kt < 4; kt++) {
            const size_t c = base + kt * 16;
            qf[0][kt][0] = *(const uint32_t*)(Qh + c);
            qf[0][kt][1] = *(const uint32_t*)(Qh + c + 8 * DMODEL);
            qf[0][kt][2] = *(const uint32_t*)(Qh + c + 8);
            qf[0][kt][3] = *(const uint32_t*)(Qh + c + 8 * DMODEL + 8);
            qf[1][kt][0] = *(const uint32_t*)(Ql + c);
            qf[1][kt][1] = *(const uint32_t*)(Ql + c + 8 * DMODEL);
            qf[1][kt][2] = *(const uint32_t*)(Ql + c + 8);
            qf[1][kt][3] = *(const uint32_t*)(Ql + c + 8 * DMODEL + 8);
        }
    }

    float o[8][4];
    #pragma unroll
    for (int nt = 0; nt < 8; nt++)
        #pragma unroll
        for (int r = 0; r < 4; r++) o[nt][r] = 0.0f;
    float m0 = -1e30f, m1 = -1e30f, l0 = 0.0f, l1 = 0.0f;

    const size_t kvbase = (size_t)b * S_ * KVD2 + kvh * HD;
    const __half* gK = KVh + kvbase;
    const __half* gV = KVh + kvbase + KVDIM;
    const int lrow = tid >> 2;
    const int lc   = tid & 3;

    auto load_tiles = [&](int buf, int lt) {
        const __half* srcK = gK + (size_t)(lt * 64 + lrow) * KVD2;
        const __half* srcV = gV + (size_t)(lt * 64 + lrow) * KVD2;
        uint32_t dK = sbase + buf * ATT_BUF_BYTES;
        uint32_t dV = dK + ATT_TILE_BYTES;
        cp16(dK + SW(lrow * 128 + lc * 16), srcK + lc * 8);
        cp16(dK + SW(lrow * 128 + (lc + 4) * 16), srcK + (lc + 4) * 8);
        cp16(dV + SW(lrow * 128 + lc * 16), srcV + lc * 8);
        cp16(dV + SW(lrow * 128 + (lc + 4) * 16), srcV + (lc + 4) * 8);
    };

    load_tiles(0, 0);
    asm volatile("cp.async.commit_group;\n");

    const int l15 = lane & 15;
    const int colh = (lane >> 4) << 4;
    const int r8 = (((lane >> 3) & 1) << 3) + (lane & 7);
    const int cpair = (lane >> 4) << 4;

    for (int lt = 0; lt < S_ / 64; lt++) {
        const int cur = lt & 1;
        if (lt + 1 < S_ / 64) load_tiles(1 - cur, lt + 1);
        asm volatile("cp.async.commit_group;\n");
        asm volatile("cp.async.wait_group 1;\n");
        __syncthreads();

        const uint32_t tbK = sbase + cur * ATT_BUF_BYTES;
        const uint32_t tbV = tbK + ATT_TILE_BYTES;

        float s[8][4];
        #pragma unroll
        for (int nt = 0; nt < 8; nt++)
            #pragma unroll
            for (int r = 0; r < 4; r++) s[nt][r] = 0.0f;

        #pragma unroll
        for (int np = 0; np < 4; np++) {
            #pragma unroll
            for (int kt = 0; kt < 4; kt++) {
                const uint32_t inner = (uint32_t)((np * 16 + l15) * 128 + kt * 32 + colh);
                uint32_t th[4];
                ldsm_x4(th, tbK + SW(inner));
                mma2(s[2*np],   qf[0][kt], th[0], th[2]);
                mma2(s[2*np+1], qf[0][kt], th[1], th[3]);
                mma2(s[2*np],   qf[1][kt], th[0], th[2]);
                mma2(s[2*np+1], qf[1][kt], th[1], th[3]);
            }
        }

        float mx0 = -1e30f, mx1 = -1e30f;
        #pragma unroll
        for (int nt = 0; nt < 8; nt++) {
            mx0 = fmaxf(mx0, fmaxf(s[nt][0], s[nt][1]));
            mx1 = fmaxf(mx1, fmaxf(s[nt][2], s[nt][3]));
        }
        mx0 = fmaxf(mx0, __shfl_xor_sync(0xffffffffu, mx0, 1));
        mx0 = fmaxf(mx0, __shfl_xor_sync(0xffffffffu, mx0, 2));
        mx1 = fmaxf(mx1, __shfl_xor_sync(0xffffffffu, mx1, 1));
        mx1 = fmaxf(mx1, __shfl_xor_sync(0xffffffffu, mx1, 2));
        const float mn0 = fmaxf(m0, mx0), mn1 = fmaxf(m1, mx1);
        const float sc0 = fexp2(m0 - mn0), sc1 = fexp2(m1 - mn1);
        m0 = mn0; m1 = mn1;
        l0 *= sc0; l1 *= sc1;
        #pragma unroll
        for (int nt = 0; nt < 8; nt++) {
            o[nt][0] *= sc0; o[nt][1] *= sc0; o[nt][2] *= sc1; o[nt][3] *= sc1;
        }
        #pragma unroll
        for (int nt = 0; nt < 8; nt++) {
            float p0 = fexp2(s[nt][0] - m0), p1 = fexp2(s[nt][1] - m0);
            float p2 = fexp2(s[nt][2] - m1), p3 = fexp2(s[nt][3] - m1);
            l0 += p0 + p1; l1 += p2 + p3;
            s[nt][0] = p0; s[nt][1] = p1; s[nt][2] = p2; s[nt][3] = p3;
        }

        uint32_t ph_[4][4], pl_[4][4];
        #pragma unroll
        for (int lk = 0; lk < 4; lk++) {
            ph_[lk][0] = packsplit_h(s[2*lk][0],   s[2*lk][1],   pl_[lk][0]);
            ph_[lk][1] = packsplit_h(s[2*lk][2],   s[2*lk][3],   pl_[lk][1]);
            ph_[lk][2] = packsplit_h(s[2*lk+1][0], s[2*lk+1][1], pl_[lk][2]);
            ph_[lk][3] = packsplit_h(s[2*lk+1][2], s[2*lk+1][3], pl_[lk][3]);
        }

        #pragma unroll
        for (int ntp = 0; ntp < 4; ntp++) {
            #pragma unroll
            for (int lk = 0; lk < 4; lk++) {
                const uint32_t inner = (uint32_t)((lk * 16 + r8) * 128 + ntp * 32 + cpair);
                uint32_t vh[4];
                ldsm_x4_t(vh, tbV + SW(inner));
                mma2(o[2*ntp],   ph_[lk], vh[0], vh[1]);
                mma2(o[2*ntp+1], ph_[lk], vh[2], vh[3]);
                mma2(o[2*ntp],   pl_[lk], vh[0], vh[1]);
                mma2(o[2*ntp+1], pl_[lk], vh[2], vh[3]);
            }
        }
        __syncthreads();
    }

    l0 += __shfl_xor_sync(0xffffffffu, l0, 1);
    l0 += __shfl_xor_sync(0xffffffffu, l0, 2);
    l1 += __shfl_xor_sync(0xffffffffu, l1, 1);
    l1 += __shfl_xor_sync(0xffffffffu, l1, 2);
    const float inv0 = 1.0f / l0, inv1 = 1.0f / l1;

    const size_t ro = ((size_t)(b * S_ + qrow + (lane >> 2))) * DMODEL + h * HD + (lane & 3) * 2;
    #pragma unroll
    for (int nt = 0; nt < 8; nt++) {
        uint32_t lo0, lo1;
        uint32_t hi0 = packsplit_h(o[nt][0] * inv0, o[nt][1] * inv0, lo0);
        uint32_t hi1 = packsplit_h(o[nt][2] * inv1, o[nt][3] * inv1, lo1);
        *(uint32_t*)(AOh + ro + nt * 8)              = hi0;
        *(uint32_t*)(AOl + ro + nt * 8)              = lo0;
        *(uint32_t*)(AOh + ro + nt * 8 + 8 * DMODEL) = hi1;
        *(uint32_t*)(AOl + ro + nt * 8 + 8 * DMODEL) = lo1;
    }
}

// ---------------------------------------------------------------------------
// Launch
// ---------------------------------------------------------------------------
extern "C" void kernel_launch(void* const* d_in, const int* in_sizes, int n_in,
                              void* d_out, int out_size)
{
    const float* h_bsd = (const float*)d_in[0];
    const float* w_q   = (const float*)d_in[1];
    const float* w_k   = (const float*)d_in[2];
    const float* w_v   = (const float*)d_in[3];
    const float* w_o   = (const float*)d_in[4];
    float* out = (float*)d_out;

    __half *W, *Xh, *Xl, *Qh, *Ql, *KVh, *AOh, *AOl;
    cudaGetSymbolAddress((void**)&W, g_W);
    cudaGetSymbolAddress((void**)&Xh, g_Xh);   cudaGetSymbolAddress((void**)&Xl, g_Xl);
    cudaGetSymbolAddress((void**)&Qh, g_Qh);   cudaGetSymbolAddress((void**)&Ql, g_Ql);
    cudaGetSymbolAddress((void**)&KVh, g_KVh);
    cudaGetSymbolAddress((void**)&AOh, g_AOh); cudaGetSymbolAddress((void**)&AOl, g_AOl);

    static int attr_set = 0;
    if (!attr_set) {
        cudaFuncSetAttribute(flash_attn_mma,
                             cudaFuncAttributeMaxDynamicSharedMemorySize, ATT_SMEM);
        cudaFuncSetAttribute(gemm_split,
                             cudaFuncAttributeMaxDynamicSharedMemorySize, GEMM_SMEM);
        attr_set = 1;
    }

    cvt_w4<<<512, 256>>>(w_q, w_k, w_v, w_o, W);
    split2_f16<<<512, 256>>>(h_bsd, Xh, Xl, MROWS * DMODEL / 4);

    // Fused QKV projection: N = 3072 over packed [Wq|Wk|Wv]
    gemm_split<<<dim3(NQKV / TCN, MROWS / TCM), 256, GEMM_SMEM>>>(
        Xh, Xl, W, nullptr, Qh, Ql, KVh, MROWS, DMODEL);

    flash_attn_mma<<<dim3(S_ / 128, NQH, B_), 256, ATT_SMEM>>>(
        Qh, Ql, KVh, AOh, AOl);

    // O projection: fp32 out
    gemm_split<<<dim3(DMODEL / TCN, MROWS / TCM), 256, GEMM_SMEM>>>(
        AOh, AOl, W + NQW + 2 * NKW, out, nullptr, nullptr, nullptr, MROWS, DMODEL);
}

// round 15
// speedup vs baseline: 1.1351x; 1.1351x over previous
#include <cuda_runtime.h>
#include <cuda_fp16.h>
#include <math.h>
#include <stdint.h>

// Problem constants
#define B_      2
#define S_      2048
#define DMODEL  2048
#define NQH     32
#define NKVH    8
#define HD      64
#define KVDIM   (NKVH * HD)   // 512
#define KVD2    (2 * KVDIM)   // 1024 (K and V fused)
#define MROWS   (B_ * S_)     // 4096
#define NQW     (DMODEL * DMODEL)
#define NKW     (KVDIM * DMODEL)

// ---------------------------------------------------------------------------
// Scratch (__device__ globals)
// g_W rows: [Wq(2048) | Wk(512) | Wv(512) | Wo(2048)] x K=2048, fp16 hi-only
// ---------------------------------------------------------------------------
__device__ __half g_W  [2 * NQW + 2 * NKW];
__device__ __half g_Xh [MROWS * DMODEL], g_Xl [MROWS * DMODEL];
__device__ __half g_Qh [MROWS * DMODEL], g_Ql [MROWS * DMODEL];
__device__ __half g_KVh[MROWS * KVD2];
__device__ __half g_AOh[MROWS * DMODEL], g_AOl[MROWS * DMODEL];

// ---------------------------------------------------------------------------
// helpers
// ---------------------------------------------------------------------------
__device__ __forceinline__ uint32_t smem_u32(const void* p) {
    return (uint32_t)__cvta_generic_to_shared(p);
}

__device__ __forceinline__ uint32_t packsplit_h(float a, float b, uint32_t& lo) {
    __half ha = __float2half_rn(a), hb = __float2half_rn(b);
    __half la = __float2half_rn(a - __half2float(ha));
    __half lb = __float2half_rn(b - __half2float(hb));
    lo = ((uint32_t)__half_as_ushort(lb) << 16) | (uint32_t)__half_as_ushort(la);
    return ((uint32_t)__half_as_ushort(hb) << 16) | (uint32_t)__half_as_ushort(ha);
}

__device__ __forceinline__ float fexp2(float x) {
    float r;
    asm("ex2.approx.f32 %0, %1;" : "=f"(r) : "f"(x));
    return r;
}

__device__ __forceinline__ void mma2(float* c, const uint32_t* a, uint32_t b0, uint32_t b1) {
    asm volatile(
        "mma.sync.aligned.m16n8k16.row.col.f32.f16.f16.f32 "
        "{%0,%1,%2,%3}, {%4,%5,%6,%7}, {%8,%9}, {%0,%1,%2,%3};"
        : "+f"(c[0]), "+f"(c[1]), "+f"(c[2]), "+f"(c[3])
        : "r"(a[0]), "r"(a[1]), "r"(a[2]), "r"(a[3]), "r"(b0), "r"(b1));
}

__device__ __forceinline__ void ldsm_x4(uint32_t* r, uint32_t addr) {
    asm volatile("ldmatrix.sync.aligned.m8n8.x4.shared.b16 {%0,%1,%2,%3}, [%4];"
                 : "=r"(r[0]), "=r"(r[1]), "=r"(r[2]), "=r"(r[3]) : "r"(addr));
}
__device__ __forceinline__ void ldsm_x4_t(uint32_t* r, uint32_t addr) {
    asm volatile("ldmatrix.sync.aligned.m8n8.x4.trans.shared.b16 {%0,%1,%2,%3}, [%4];"
                 : "=r"(r[0]), "=r"(r[1]), "=r"(r[2]), "=r"(r[3]) : "r"(addr));
}

#define SW(a) ((a) ^ (((a) >> 3) & 0x70))

__device__ __forceinline__ void cp16(uint32_t d, const void* s) {
    asm volatile("cp.async.cg.shared.global [%0], [%1], 16;\n" :: "r"(d), "l"(s));
}

#define QSCALE 0.18033688011112042f   // 1/sqrt(64) * log2(e)

// ---------------------------------------------------------------------------
// Weight convert (hi-only fp16) into packed g_W
// ---------------------------------------------------------------------------
__global__ void cvt_w4(const float* __restrict__ wq, const float* __restrict__ wk,
                       const float* __restrict__ wv, const float* __restrict__ wo,
                       __half* __restrict__ W)
{
    const int total2 = (2 * NQW + 2 * NKW) / 2;
    for (int i = blockIdx.x * blockDim.x + threadIdx.x; i < total2;
         i += gridDim.x * blockDim.x) {
        const int idx = i * 2;
        const float* src; int off;
        if (idx < NQW)                 { src = wq; off = idx; }
        else if (idx < NQW + NKW)      { src = wk; off = idx - NQW; }
        else if (idx < NQW + 2 * NKW)  { src = wv; off = idx - NQW - NKW; }
        else                           { src = wo; off = idx - NQW - 2 * NKW; }
        float2 v = *(const float2*)(src + off);
        __half2 h; h.x = __float2half_rn(v.x); h.y = __float2half_rn(v.y);
        *(__half2*)(W + idx) = h;
    }
}

// ---------------------------------------------------------------------------
// X: fp32 -> (hi, lo) fp16 buffers.
// ---------------------------------------------------------------------------
__global__ void split2_f16(const float* __restrict__ X,
                           __half* __restrict__ Yh, __half* __restrict__ Yl, int total4)
{
    for (int i = blockIdx.x * blockDim.x + threadIdx.x; i < total4;
         i += gridDim.x * blockDim.x) {
        const int idx = i * 4;
        float4 x = *(const float4*)(X + idx);
        uint32_t lo0, lo1;
        uint32_t hi0 = packsplit_h(x.x, x.y, lo0);
        uint32_t hi1 = packsplit_h(x.z, x.w, lo1);
        *(uint2*)(Yh + idx) = make_uint2(hi0, hi1);
        *(uint2*)(Yl + idx) = make_uint2(lo0, lo1);
    }
}

// ---------------------------------------------------------------------------
// Split-precision GEMM (r13 config — measured best):
//   C[M,N] = (Ah+Al)[M,K] * Bh[N,K]^T
// CTA 128x256, 512 threads, 16 warps (4M x 4N) at 32x64, TCK=64, 2-stage.
// ---------------------------------------------------------------------------
#define TCM 128
#define TCN 256
#define TCK 64
#define GA_AL 16384
#define GA_BH 32768
#define STAGE_BYTES 65536
#define GEMM_SMEM (2 * STAGE_BYTES)    // 131072

__global__ void __launch_bounds__(512, 1) gemm_split(
    const __half* __restrict__ Ah, const __half* __restrict__ Al,
    const __half* __restrict__ Bh,
    float* __restrict__ C,
    __half* __restrict__ Chi, __half* __restrict__ Clo,
    float cscale, int M, int N, int Kk)
{
    extern __shared__ __align__(1024) char sm[];
    const uint32_t sb = smem_u32(sm);

    const int tid  = threadIdx.x;
    const int lane = tid & 31;
    const int w    = tid >> 5;
    const int wm   = (w & 3) * 32;
    const int wn   = (w >> 2) * 64;
    const int bm   = blockIdx.y * TCM;
    const int bn   = blockIdx.x * TCN;

    float acc[2][8][4];
    #pragma unroll
    for (int mi = 0; mi < 2; mi++)
        #pragma unroll
        for (int nt = 0; nt < 8; nt++)
            #pragma unroll
            for (int r = 0; r < 4; r++) acc[mi][nt][r] = 0.0f;

    const int arow = tid >> 2, ach = (tid & 3) * 2;
    const int brow = tid >> 1, bch = (tid & 1) * 4;
    const __half* gAh = Ah + (size_t)(bm + arow) * Kk + ach * 8;
    const __half* gAl = Al + (size_t)(bm + arow) * Kk + ach * 8;
    const __half* gBh = Bh + (size_t)(bn + brow) * Kk + bch * 8;

    auto load_stage = [&](int buf, int kt) {
        const uint32_t st = sb + buf * STAGE_BYTES;
        const int k0 = kt * TCK;
        #pragma unroll
        for (int j = 0; j < 2; j++) {
            const uint32_t d = SW((uint32_t)(arow * 128 + (ach + j) * 16));
            cp16(st + d, gAh + k0 + j * 8);
            cp16(st + GA_AL + d, gAl + k0 + j * 8);
        }
        #pragma unroll
        for (int j = 0; j < 4; j++) {
            const uint32_t d = SW((uint32_t)(brow * 128 + (bch + j) * 16));
            cp16(st + GA_BH + d, gBh + k0 + j * 8);
        }
    };

    const int NT = Kk / TCK;
    load_stage(0, 0);
    asm volatile("cp.async.commit_group;\n");

    const int l15 = lane & 15;
    const int colh = (lane >> 4) << 4;

    for (int kt = 0; kt < NT; kt++) {
        const int cur = kt & 1;
        if (kt + 1 < NT) {
            load_stage(1 - cur, kt + 1);
            asm volatile("cp.async.commit_group;\n");
            asm volatile("cp.async.wait_group 1;\n");
        } else {
            asm volatile("cp.async.wait_group 0;\n");
        }
        __syncthreads();

        const uint32_t st = sb + cur * STAGE_BYTES;

        #pragma unroll
        for (int kk = 0; kk < 4; kk++) {
            const uint32_t colb = (uint32_t)(kk * 32 + colh);
            uint32_t ah[2][4], al[2][4];
            #pragma unroll
            for (int mi = 0; mi < 2; mi++) {
                const uint32_t off = SW((uint32_t)((wm + mi * 16 + l15) * 128) + colb);
                ldsm_x4(ah[mi], st + off);
                ldsm_x4(al[mi], st + GA_AL + off);
            }
            #pragma unroll
            for (int np = 0; np < 4; np++) {
                const uint32_t offb = SW((uint32_t)((wn + np * 16 + l15) * 128) + colb);
                uint32_t t[4];
                ldsm_x4(t, st + GA_BH + offb);
                mma2(acc[0][2*np],   ah[0], t[0], t[2]);
                mma2(acc[0][2*np+1], ah[0], t[1], t[3]);
                mma2(acc[1][2*np],   ah[1], t[0], t[2]);
                mma2(acc[1][2*np+1], ah[1], t[1], t[3]);
                mma2(acc[0][2*np],   al[0], t[0], t[2]);
                mma2(acc[0][2*np+1], al[0], t[1], t[3]);
                mma2(acc[1][2*np],   al[1], t[0], t[2]);
                mma2(acc[1][2*np+1], al[1], t[1], t[3]);
            }
        }
        __syncthreads();
    }

    if (C) {
        #pragma unroll
        for (int mi = 0; mi < 2; mi++) {
            const int r0 = bm + wm + mi * 16 + (lane >> 2);
            #pragma unroll
            for (int nt = 0; nt < 8; nt++) {
                const int c0 = bn + wn + nt * 8 + 2 * (lane & 3);
                *(float2*)(C + (size_t)r0 * N + c0)       = make_float2(acc[mi][nt][0], acc[mi][nt][1]);
                *(float2*)(C + (size_t)(r0 + 8) * N + c0) = make_float2(acc[mi][nt][2], acc[mi][nt][3]);
            }
        }
    } else if (Clo) {
        #pragma unroll
        for (int mi = 0; mi < 2; mi++) {
            const int r0 = bm + wm + mi * 16 + (lane >> 2);
            #pragma unroll
            for (int nt = 0; nt < 8; nt++) {
                const int c0 = bn + wn + nt * 8 + 2 * (lane & 3);
                uint32_t lo0, lo1;
                uint32_t hi0 = packsplit_h(acc[mi][nt][0] * cscale, acc[mi][nt][1] * cscale, lo0);
                uint32_t hi1 = packsplit_h(acc[mi][nt][2] * cscale, acc[mi][nt][3] * cscale, lo1);
                *(uint32_t*)(Chi + (size_t)r0 * N + c0)       = hi0;
                *(uint32_t*)(Clo + (size_t)r0 * N + c0)       = lo0;
                *(uint32_t*)(Chi + (size_t)(r0 + 8) * N + c0) = hi1;
                *(uint32_t*)(Clo + (size_t)(r0 + 8) * N + c0) = lo1;
            }
        }
    } else {
        #pragma unroll
        for (int mi = 0; mi < 2; mi++) {
            const int r0 = bm + wm + mi * 16 + (lane >> 2);
            #pragma unroll
            for (int nt = 0; nt < 8; nt++) {
                const int c0 = bn + wn + nt * 8 + 2 * (lane & 3);
                __half2 h0, h1;
                h0.x = __float2half_rn(acc[mi][nt][0]); h0.y = __float2half_rn(acc[mi][nt][1]);
                h1.x = __float2half_rn(acc[mi][nt][2]); h1.y = __float2half_rn(acc[mi][nt][3]);
                *(__half2*)(Chi + (size_t)r0 * N + c0)       = h0;
                *(__half2*)(Chi + (size_t)(r0 + 8) * N + c0) = h1;
            }
        }
    }
}

// ---------------------------------------------------------------------------
// fp16 flash attention, restructured: each 64-row KV tile processed in two
// 32-row halves (s[4][4], ph/pl[2][4] -> ~32 fewer live regs), forced to
// 2 CTAs/SM via launch bounds.
// ---------------------------------------------------------------------------
#define ATT_TILE_BYTES 8192
#define ATT_BUF_BYTES  (2 * ATT_TILE_BYTES)
#define ATT_SMEM       (2 * ATT_BUF_BYTES)   // 32768

__global__ void __launch_bounds__(256, 2) flash_attn_mma(
    const __half* __restrict__ Qh, const __half* __restrict__ Ql,
    const __half* __restrict__ KVh,
    __half* __restrict__ AOh, __half* __restrict__ AOl)
{
    extern __shared__ __half smem[];
    const uint32_t sbase = smem_u32(smem);

    const int b    = blockIdx.z;
    const int h    = blockIdx.y;
    const int kvh  = h >> 2;
    const int tid  = threadIdx.x;
    const int lane = tid & 31;
    const int w    = tid >> 5;
    const int qrow = blockIdx.x * 128 + w * 16;

    uint32_t qf[2][4][4];
    {
        const size_t base = ((size_t)(b * S_ + qrow + (lane >> 2))) * DMODEL + h * HD + (lane & 3) * 2;
        #pragma unroll
        for (int kt = 0; kt < 4; kt++) {
            const size_t c = base + kt * 16;
            qf[0][kt][0] = *(const uint32_t*)(Qh + c);
            qf[0][kt][1] = *(const uint32_t*)(Qh + c + 8 * DMODEL);
            qf[0][kt][2] = *(const uint32_t*)(Qh + c + 8);
            qf[0][kt][3] = *(const uint32_t*)(Qh + c + 8 * DMODEL + 8);
            qf[1][kt][0] = *(const uint32_t*)(Ql + c);
            qf[1][kt][1] = *(const uint32_t*)(Ql + c + 8 * DMODEL);
            qf[1][kt][2] = *(const uint32_t*)(Ql + c + 8);
            qf[1][kt][3] = *(const uint32_t*)(Ql + c + 8 * DMODEL + 8);
        }
    }

    float o[8][4];
    #pragma unroll
    for (int nt = 0; nt < 8; nt++)
        #pragma unroll
        for (int r = 0; r < 4; r++) o[nt][r] = 0.0f;
    float m0 = -1e30f, m1 = -1e30f, l0 = 0.0f, l1 = 0.0f;

    const size_t kvbase = (size_t)b * S_ * KVD2 + kvh * HD;
    const __half* gK = KVh + kvbase;
    const __half* gV = KVh + kvbase + KVDIM;
    const int lrow = tid >> 2;
    const int lc   = tid & 3;

    auto load_tiles = [&](int buf, int lt) {
        const __half* srcK = gK + (size_t)(lt * 64 + lrow) * KVD2;
        const __half* srcV = gV + (size_t)(lt * 64 + lrow) * KVD2;
        uint32_t dK = sbase + buf * ATT_BUF_BYTES;
        uint32_t dV = dK + ATT_TILE_BYTES;
        cp16(dK + SW(lrow * 128 + lc * 16), srcK + lc * 8);
        cp16(dK + SW(lrow * 128 + (lc + 4) * 16), srcK + (lc + 4) * 8);
        cp16(dV + SW(lrow * 128 + lc * 16), srcV + lc * 8);
        cp16(dV + SW(lrow * 128 + (lc + 4) * 16), srcV + (lc + 4) * 8);
    };

    load_tiles(0, 0);
    asm volatile("cp.async.commit_group;\n");

    const int l15 = lane & 15;
    const int colh = (lane >> 4) << 4;
    const int r8 = (((lane >> 3) & 1) << 3) + (lane & 7);
    const int cpair = (lane >> 4) << 4;

    for (int lt = 0; lt < S_ / 64; lt++) {
        const int cur = lt & 1;
        if (lt + 1 < S_ / 64) load_tiles(1 - cur, lt + 1);
        asm volatile("cp.async.commit_group;\n");
        asm volatile("cp.async.wait_group 1;\n");
        __syncthreads();

        const uint32_t tbK = sbase + cur * ATT_BUF_BYTES;
        const uint32_t tbV = tbK + ATT_TILE_BYTES;

        #pragma unroll
        for (int half = 0; half < 2; half++) {
            float s[4][4];
            #pragma unroll
            for (int nt = 0; nt < 4; nt++)
                #pragma unroll
                for (int r = 0; r < 4; r++) s[nt][r] = 0.0f;

            // ---- S-half = (Qh+Ql) Kh^T over k-rows [half*32, half*32+32)
            #pragma unroll
            for (int np = 0; np < 2; np++) {
                #pragma unroll
                for (int kt = 0; kt < 4; kt++) {
                    const uint32_t inner =
                        (uint32_t)((half * 32 + np * 16 + l15) * 128 + kt * 32 + colh);
                    uint32_t th[4];
                    ldsm_x4(th, tbK + SW(inner));
                    mma2(s[2*np],   qf[0][kt], th[0], th[2]);
                    mma2(s[2*np+1], qf[0][kt], th[1], th[3]);
                    mma2(s[2*np],   qf[1][kt], th[0], th[2]);
                    mma2(s[2*np+1], qf[1][kt], th[1], th[3]);
                }
            }

            // ---- online softmax partial update
            float mx0 = -1e30f, mx1 = -1e30f;
            #pragma unroll
            for (int nt = 0; nt < 4; nt++) {
                mx0 = fmaxf(mx0, fmaxf(s[nt][0], s[nt][1]));
                mx1 = fmaxf(mx1, fmaxf(s[nt][2], s[nt][3]));
            }
            mx0 = fmaxf(mx0, __shfl_xor_sync(0xffffffffu, mx0, 1));
            mx0 = fmaxf(mx0, __shfl_xor_sync(0xffffffffu, mx0, 2));
            mx1 = fmaxf(mx1, __shfl_xor_sync(0xffffffffu, mx1, 1));
            mx1 = fmaxf(mx1, __shfl_xor_sync(0xffffffffu, mx1, 2));
            const float mn0 = fmaxf(m0, mx0), mn1 = fmaxf(m1, mx1);
            const float sc0 = fexp2(m0 - mn0), sc1 = fexp2(m1 - mn1);
            m0 = mn0; m1 = mn1;
            l0 *= sc0; l1 *= sc1;
            #pragma unroll
            for (int nt = 0; nt < 8; nt++) {
                o[nt][0] *= sc0; o[nt][1] *= sc0; o[nt][2] *= sc1; o[nt][3] *= sc1;
            }
            #pragma unroll
            for (int nt = 0; nt < 4; nt++) {
                float p0 = fexp2(s[nt][0] - m0), p1 = fexp2(s[nt][1] - m0);
                float p2 = fexp2(s[nt][2] - m1), p3 = fexp2(s[nt][3] - m1);
                l0 += p0 + p1; l1 += p2 + p3;
                s[nt][0] = p0; s[nt][1] = p1; s[nt][2] = p2; s[nt][3] = p3;
            }

            uint32_t ph_[2][4], pl_[2][4];
            #pragma unroll
            for (int lk = 0; lk < 2; lk++) {
                ph_[lk][0] = packsplit_h(s[2*lk][0],   s[2*lk][1],   pl_[lk][0]);
                ph_[lk][1] = packsplit_h(s[2*lk][2],   s[2*lk][3],   pl_[lk][1]);
                ph_[lk][2] = packsplit_h(s[2*lk+1][0], s[2*lk+1][1], pl_[lk][2]);
                ph_[lk][3] = packsplit_h(s[2*lk+1][2], s[2*lk+1][3], pl_[lk][3]);
            }

            // ---- O += (Ph+Pl) Vh over the same 32 k-rows
            #pragma unroll
            for (int ntp = 0; ntp < 4; ntp++) {
                #pragma unroll
                for (int lk = 0; lk < 2; lk++) {
                    const uint32_t inner =
                        (uint32_t)((half * 32 + lk * 16 + r8) * 128 + ntp * 32 + cpair);
                    uint32_t vh[4];
                    ldsm_x4_t(vh, tbV + SW(inner));
                    mma2(o[2*ntp],   ph_[lk], vh[0], vh[1]);
                    mma2(o[2*ntp+1], ph_[lk], vh[2], vh[3]);
                    mma2(o[2*ntp],   pl_[lk], vh[0], vh[1]);
                    mma2(o[2*ntp+1], pl_[lk], vh[2], vh[3]);
                }
            }
        }
        __syncthreads();
    }

    l0 += __shfl_xor_sync(0xffffffffu, l0, 1);
    l0 += __shfl_xor_sync(0xffffffffu, l0, 2);
    l1 += __shfl_xor_sync(0xffffffffu, l1, 1);
    l1 += __shfl_xor_sync(0xffffffffu, l1, 2);
    const float inv0 = 1.0f / l0, inv1 = 1.0f / l1;

    const size_t ro = ((size_t)(b * S_ + qrow + (lane >> 2))) * DMODEL + h * HD + (lane & 3) * 2;
    #pragma unroll
    for (int nt = 0; nt < 8; nt++) {
        uint32_t lo0, lo1;
        uint32_t hi0 = packsplit_h(o[nt][0] * inv0, o[nt][1] * inv0, lo0);
        uint32_t hi1 = packsplit_h(o[nt][2] * inv1, o[nt][3] * inv1, lo1);
        *(uint32_t*)(AOh + ro + nt * 8)              = hi0;
        *(uint32_t*)(AOl + ro + nt * 8)              = lo0;
        *(uint32_t*)(AOh + ro + nt * 8 + 8 * DMODEL) = hi1;
        *(uint32_t*)(AOl + ro + nt * 8 + 8 * DMODEL) = lo1;
    }
}

// ---------------------------------------------------------------------------
// Launch  (r13 launch structure)
// ---------------------------------------------------------------------------
extern "C" void kernel_launch(void* const* d_in, const int* in_sizes, int n_in,
                              void* d_out, int out_size)
{
    const float* h_bsd = (const float*)d_in[0];
    const float* w_q   = (const float*)d_in[1];
    const float* w_k   = (const float*)d_in[2];
    const float* w_v   = (const float*)d_in[3];
    const float* w_o   = (const float*)d_in[4];
    float* out = (float*)d_out;

    __half *W, *Xh, *Xl, *Qh, *Ql, *KVh, *AOh, *AOl;
    cudaGetSymbolAddress((void**)&W, g_W);
    cudaGetSymbolAddress((void**)&Xh, g_Xh);   cudaGetSymbolAddress((void**)&Xl, g_Xl);
    cudaGetSymbolAddress((void**)&Qh, g_Qh);   cudaGetSymbolAddress((void**)&Ql, g_Ql);
    cudaGetSymbolAddress((void**)&KVh, g_KVh);
    cudaGetSymbolAddress((void**)&AOh, g_AOh); cudaGetSymbolAddress((void**)&AOl, g_AOl);

    static int attr_set = 0;
    if (!attr_set) {
        cudaFuncSetAttribute(flash_attn_mma,
                             cudaFuncAttributeMaxDynamicSharedMemorySize, ATT_SMEM);
        cudaFuncSetAttribute(gemm_split,
                             cudaFuncAttributeMaxDynamicSharedMemorySize, GEMM_SMEM);
        attr_set = 1;
    }

    cvt_w4<<<512, 256>>>(w_q, w_k, w_v, w_o, W);
    split2_f16<<<512, 256>>>(h_bsd, Xh, Xl, MROWS * DMODEL / 4);

    // Q projection (scaled, 2-term fp16 out), fused KV projection (1-term out)
    gemm_split<<<dim3(DMODEL / TCN, MROWS / TCM), 512, GEMM_SMEM>>>(
        Xh, Xl, W, nullptr, Qh, Ql, QSCALE, MROWS, DMODEL, DMODEL);
    gemm_split<<<dim3(KVD2 / TCN, MROWS / TCM), 512, GEMM_SMEM>>>(
        Xh, Xl, W + NQW, nullptr, KVh, nullptr, 1.0f, MROWS, KVD2, DMODEL);

    flash_attn_mma<<<dim3(S_ / 128, NQH, B_), 256, ATT_SMEM>>>(
        Qh, Ql, KVh, AOh, AOl);

    gemm_split<<<dim3(DMODEL / TCN, MROWS / TCM), 512, GEMM_SMEM>>>(
        AOh, AOl, W + NQW + 2 * NKW, out, nullptr, nullptr, 1.0f, MROWS, DMODEL, DMODEL);
}

// round 16
// speedup vs baseline: 1.1485x; 1.0118x over previous
#include <cuda_runtime.h>
#include <cuda_fp16.h>
#include <math.h>
#include <stdint.h>

// Problem constants
#define B_      2
#define S_      2048
#define DMODEL  2048
#define NQH     32
#define NKVH    8
#define HD      64
#define KVDIM   (NKVH * HD)   // 512
#define KVD2    (2 * KVDIM)   // 1024 (K and V fused)
#define MROWS   (B_ * S_)     // 4096
#define NQW     (DMODEL * DMODEL)
#define NKW     (KVDIM * DMODEL)

// ---------------------------------------------------------------------------
// Scratch (__device__ globals)
// g_W rows: [Wq(2048) | Wk(512) | Wv(512) | Wo(2048)] x K=2048, fp16 hi-only
// ---------------------------------------------------------------------------
__device__ __half g_W  [2 * NQW + 2 * NKW];
__device__ __half g_Xh [MROWS * DMODEL], g_Xl [MROWS * DMODEL];
__device__ __half g_Qh [MROWS * DMODEL], g_Ql [MROWS * DMODEL];
__device__ __half g_KVh[MROWS * KVD2];
__device__ __half g_AOh[MROWS * DMODEL];

// ---------------------------------------------------------------------------
// helpers
// ---------------------------------------------------------------------------
__device__ __forceinline__ uint32_t smem_u32(const void* p) {
    return (uint32_t)__cvta_generic_to_shared(p);
}

__device__ __forceinline__ uint32_t packsplit_h(float a, float b, uint32_t& lo) {
    __half ha = __float2half_rn(a), hb = __float2half_rn(b);
    __half la = __float2half_rn(a - __half2float(ha));
    __half lb = __float2half_rn(b - __half2float(hb));
    lo = ((uint32_t)__half_as_ushort(lb) << 16) | (uint32_t)__half_as_ushort(la);
    return ((uint32_t)__half_as_ushort(hb) << 16) | (uint32_t)__half_as_ushort(ha);
}

__device__ __forceinline__ float fexp2(float x) {
    float r;
    asm("ex2.approx.f32 %0, %1;" : "=f"(r) : "f"(x));
    return r;
}

__device__ __forceinline__ void mma2(float* c, const uint32_t* a, uint32_t b0, uint32_t b1) {
    asm volatile(
        "mma.sync.aligned.m16n8k16.row.col.f32.f16.f16.f32 "
        "{%0,%1,%2,%3}, {%4,%5,%6,%7}, {%8,%9}, {%0,%1,%2,%3};"
        : "+f"(c[0]), "+f"(c[1]), "+f"(c[2]), "+f"(c[3])
        : "r"(a[0]), "r"(a[1]), "r"(a[2]), "r"(a[3]), "r"(b0), "r"(b1));
}

__device__ __forceinline__ void ldsm_x4(uint32_t* r, uint32_t addr) {
    asm volatile("ldmatrix.sync.aligned.m8n8.x4.shared.b16 {%0,%1,%2,%3}, [%4];"
                 : "=r"(r[0]), "=r"(r[1]), "=r"(r[2]), "=r"(r[3]) : "r"(addr));
}
__device__ __forceinline__ void ldsm_x4_t(uint32_t* r, uint32_t addr) {
    asm volatile("ldmatrix.sync.aligned.m8n8.x4.trans.shared.b16 {%0,%1,%2,%3}, [%4];"
                 : "=r"(r[0]), "=r"(r[1]), "=r"(r[2]), "=r"(r[3]) : "r"(addr));
}

#define SW(a) ((a) ^ (((a) >> 3) & 0x70))

__device__ __forceinline__ void cp16(uint32_t d, const void* s) {
    asm volatile("cp.async.cg.shared.global [%0], [%1], 16;\n" :: "r"(d), "l"(s));
}

#define QSCALE 0.18033688011112042f   // 1/sqrt(64) * log2(e)

// ---------------------------------------------------------------------------
// Weight convert (hi-only fp16) into packed g_W
// ---------------------------------------------------------------------------
__global__ void cvt_w4(const float* __restrict__ wq, const float* __restrict__ wk,
                       const float* __restrict__ wv, const float* __restrict__ wo,
                       __half* __restrict__ W)
{
    const int total2 = (2 * NQW + 2 * NKW) / 2;
    for (int i = blockIdx.x * blockDim.x + threadIdx.x; i < total2;
         i += gridDim.x * blockDim.x) {
        const int idx = i * 2;
        const float* src; int off;
        if (idx < NQW)                 { src = wq; off = idx; }
        else if (idx < NQW + NKW)      { src = wk; off = idx - NQW; }
        else if (idx < NQW + 2 * NKW)  { src = wv; off = idx - NQW - NKW; }
        else                           { src = wo; off = idx - NQW - 2 * NKW; }
        float2 v = *(const float2*)(src + off);
        __half2 h; h.x = __float2half_rn(v.x); h.y = __float2half_rn(v.y);
        *(__half2*)(W + idx) = h;
    }
}

// ---------------------------------------------------------------------------
// X: fp32 -> (hi, lo) fp16 buffers.
// ---------------------------------------------------------------------------
__global__ void split2_f16(const float* __restrict__ X,
                           __half* __restrict__ Yh, __half* __restrict__ Yl, int total4)
{
    for (int i = blockIdx.x * blockDim.x + threadIdx.x; i < total4;
         i += gridDim.x * blockDim.x) {
        const int idx = i * 4;
        float4 x = *(const float4*)(X + idx);
        uint32_t lo0, lo1;
        uint32_t hi0 = packsplit_h(x.x, x.y, lo0);
        uint32_t hi1 = packsplit_h(x.z, x.w, lo1);
        *(uint2*)(Yh + idx) = make_uint2(hi0, hi1);
        *(uint2*)(Yl + idx) = make_uint2(lo0, lo1);
    }
}

// ---------------------------------------------------------------------------
// Split-precision GEMM, CTA 128x256, 512 threads, 16 warps (4M x 4N) at
// 32x64, TCK=64, 3-stage cp.async ring (192 KB smem).
//   acc = (Ah [+ Al]) * Bh^T     (Al == nullptr -> 1-term)
// B rows are globally indexed into the packed weight buffer.
// Output modes (CTA-uniform):
//   C != 0          : fp32 out, stride Nq  (O-projection)
//   C == 0, bn < Nq : Q out — 2-term fp16 (Qhi/Qlo), scaled QSCALE, stride Nq
//   C == 0, bn >= Nq: KV out — 1-term fp16 (KVhi), stride KVD2
// ---------------------------------------------------------------------------
#define TCM 128
#define TCN 256
#define TCK 64
#define GA_AL 16384
#define GA_BH 32768
#define STAGE_BYTES 65536
#define GEMM_SMEM (3 * STAGE_BYTES)    // 196608

__global__ void __launch_bounds__(512, 1) gemm_split(
    const __half* __restrict__ Ah, const __half* __restrict__ Al,
    const __half* __restrict__ Bh,
    float* __restrict__ C,
    __half* __restrict__ Qhi, __half* __restrict__ Qlo,
    __half* __restrict__ KVhi,
    int M, int Kk, int Nq)
{
    extern __shared__ __align__(1024) char sm[];
    const uint32_t sb = smem_u32(sm);

    const int tid  = threadIdx.x;
    const int lane = tid & 31;
    const int w    = tid >> 5;
    const int wm   = (w & 3) * 32;
    const int wn   = (w >> 2) * 64;
    const int bm   = blockIdx.y * TCM;
    const int bn   = blockIdx.x * TCN;
    const bool two_term = (Al != nullptr);

    float acc[2][8][4];
    #pragma unroll
    for (int mi = 0; mi < 2; mi++)
        #pragma unroll
        for (int nt = 0; nt < 8; nt++)
            #pragma unroll
            for (int r = 0; r < 4; r++) acc[mi][nt][r] = 0.0f;

    const int arow = tid >> 2, ach = (tid & 3) * 2;
    const int brow = tid >> 1, bch = (tid & 1) * 4;
    const __half* gAh = Ah + (size_t)(bm + arow) * Kk + ach * 8;
    const __half* gAl = two_term ? (Al + (size_t)(bm + arow) * Kk + ach * 8) : gAh;
    const __half* gBh = Bh + (size_t)(bn + brow) * Kk + bch * 8;

    auto load_stage = [&](int buf, int kt) {
        const uint32_t st = sb + buf * STAGE_BYTES;
        const int k0 = kt * TCK;
        #pragma unroll
        for (int j = 0; j < 2; j++) {
            const uint32_t d = SW((uint32_t)(arow * 128 + (ach + j) * 16));
            cp16(st + d, gAh + k0 + j * 8);
            if (two_term) cp16(st + GA_AL + d, gAl + k0 + j * 8);
        }
        #pragma unroll
        for (int j = 0; j < 4; j++) {
            const uint32_t d = SW((uint32_t)(brow * 128 + (bch + j) * 16));
            cp16(st + GA_BH + d, gBh + k0 + j * 8);
        }
    };

    const int NT = Kk / TCK;
    load_stage(0, 0);
    asm volatile("cp.async.commit_group;\n");
    load_stage(1, 1);
    asm volatile("cp.async.commit_group;\n");

    const int l15 = lane & 15;
    const int colh = (lane >> 4) << 4;

    for (int kt = 0; kt < NT; kt++) {
        if (kt + 2 < NT) {
            load_stage((kt + 2) % 3, kt + 2);
            asm volatile("cp.async.commit_group;\n");
            asm volatile("cp.async.wait_group 2;\n");
        } else {
            asm volatile("cp.async.wait_group 0;\n");
        }
        __syncthreads();

        const uint32_t st = sb + (kt % 3) * STAGE_BYTES;

        #pragma unroll
        for (int kk = 0; kk < 4; kk++) {
            const uint32_t colb = (uint32_t)(kk * 32 + colh);
            uint32_t ah[2][4], al[2][4];
            #pragma unroll
            for (int mi = 0; mi < 2; mi++) {
                const uint32_t off = SW((uint32_t)((wm + mi * 16 + l15) * 128) + colb);
                ldsm_x4(ah[mi], st + off);
                if (two_term) ldsm_x4(al[mi], st + GA_AL + off);
            }
            #pragma unroll
            for (int np = 0; np < 4; np++) {
                const uint32_t offb = SW((uint32_t)((wn + np * 16 + l15) * 128) + colb);
                uint32_t t[4];
                ldsm_x4(t, st + GA_BH + offb);
                mma2(acc[0][2*np],   ah[0], t[0], t[2]);
                mma2(acc[0][2*np+1], ah[0], t[1], t[3]);
                mma2(acc[1][2*np],   ah[1], t[0], t[2]);
                mma2(acc[1][2*np+1], ah[1], t[1], t[3]);
                if (two_term) {
                    mma2(acc[0][2*np],   al[0], t[0], t[2]);
                    mma2(acc[0][2*np+1], al[0], t[1], t[3]);
                    mma2(acc[1][2*np],   al[1], t[0], t[2]);
                    mma2(acc[1][2*np+1], al[1], t[1], t[3]);
                }
            }
        }
        __syncthreads();
    }

    // ---- epilogue (CTA-uniform branch)
    if (C) {
        #pragma unroll
        for (int mi = 0; mi < 2; mi++) {
            const int r0 = bm + wm + mi * 16 + (lane >> 2);
            #pragma unroll
            for (int nt = 0; nt < 8; nt++) {
                const int c0 = bn + wn + nt * 8 + 2 * (lane & 3);
                *(float2*)(C + (size_t)r0 * Nq + c0)       = make_float2(acc[mi][nt][0], acc[mi][nt][1]);
                *(float2*)(C + (size_t)(r0 + 8) * Nq + c0) = make_float2(acc[mi][nt][2], acc[mi][nt][3]);
            }
        }
    } else if (bn < Nq) {
        #pragma unroll
        for (int mi = 0; mi < 2; mi++) {
            const int r0 = bm + wm + mi * 16 + (lane >> 2);
            #pragma unroll
            for (int nt = 0; nt < 8; nt++) {
                const int c0 = bn + wn + nt * 8 + 2 * (lane & 3);
                uint32_t lo0, lo1;
                uint32_t hi0 = packsplit_h(acc[mi][nt][0] * QSCALE, acc[mi][nt][1] * QSCALE, lo0);
                uint32_t hi1 = packsplit_h(acc[mi][nt][2] * QSCALE, acc[mi][nt][3] * QSCALE, lo1);
                *(uint32_t*)(Qhi + (size_t)r0 * Nq + c0)       = hi0;
                *(uint32_t*)(Qlo + (size_t)r0 * Nq + c0)       = lo0;
                *(uint32_t*)(Qhi + (size_t)(r0 + 8) * Nq + c0) = hi1;
                *(uint32_t*)(Qlo + (size_t)(r0 + 8) * Nq + c0) = lo1;
            }
        }
    } else {
        #pragma unroll
        for (int mi = 0; mi < 2; mi++) {
            const int r0 = bm + wm + mi * 16 + (lane >> 2);
            #pragma unroll
            for (int nt = 0; nt < 8; nt++) {
                const int c0 = bn - Nq + wn + nt * 8 + 2 * (lane & 3);
                __half2 h0, h1;
                h0.x = __float2half_rn(acc[mi][nt][0]); h0.y = __float2half_rn(acc[mi][nt][1]);
                h1.x = __float2half_rn(acc[mi][nt][2]); h1.y = __float2half_rn(acc[mi][nt][3]);
                *(__half2*)(KVhi + (size_t)r0 * KVD2 + c0)       = h0;
                *(__half2*)(KVhi + (size_t)(r0 + 8) * KVD2 + c0) = h1;
            }
        }
    }
}

// ---------------------------------------------------------------------------
// fp16 flash attention (r15 halved-tile structure); epilogue writes hi only.
// ---------------------------------------------------------------------------
#define ATT_TILE_BYTES 8192
#define ATT_BUF_BYTES  (2 * ATT_TILE_BYTES)
#define ATT_SMEM       (2 * ATT_BUF_BYTES)   // 32768

__global__ void __launch_bounds__(256, 2) flash_attn_mma(
    const __half* __restrict__ Qh, const __half* __restrict__ Ql,
    const __half* __restrict__ KVh,
    __half* __restrict__ AOh)
{
    extern __shared__ __half smem[];
    const uint32_t sbase = smem_u32(smem);

    const int b    = blockIdx.z;
    const int h    = blockIdx.y;
    const int kvh  = h >> 2;
    const int tid  = threadIdx.x;
    const int lane = tid & 31;
    const int w    = tid >> 5;
    const int qrow = blockIdx.x * 128 + w * 16;

    uint32_t qf[2][4][4];
    {
        const size_t base = ((size_t)(b * S_ + qrow + (lane >> 2))) * DMODEL + h * HD + (lane & 3) * 2;
        #pragma unroll
        for (int kt = 0; kt < 4; kt++) {
            const size_t c = base + kt * 16;
            qf[0][kt][0] = *(const uint32_t*)(Qh + c);
            qf[0][kt][1] = *(const uint32_t*)(Qh + c + 8 * DMODEL);
            qf[0][kt][2] = *(const uint32_t*)(Qh + c + 8);
            qf[0][kt][3] = *(const uint32_t*)(Qh + c + 8 * DMODEL + 8);
            qf[1][kt][0] = *(const uint32_t*)(Ql + c);
            qf[1][kt][1] = *(const uint32_t*)(Ql + c + 8 * DMODEL);
            qf[1][kt][2] = *(const uint32_t*)(Ql + c + 8);
            qf[1][kt][3] = *(const uint32_t*)(Ql + c + 8 * DMODEL + 8);
        }
    }

    float o[8][4];
    #pragma unroll
    for (int nt = 0; nt < 8; nt++)
        #pragma unroll
        for (int r = 0; r < 4; r++) o[nt][r] = 0.0f;
    float m0 = -1e30f, m1 = -1e30f, l0 = 0.0f, l1 = 0.0f;

    const size_t kvbase = (size_t)b * S_ * KVD2 + kvh * HD;
    const __half* gK = KVh + kvbase;
    const __half* gV = KVh + kvbase + KVDIM;
    const int lrow = tid >> 2;
    const int lc   = tid & 3;

    auto load_tiles = [&](int buf, int lt) {
        const __half* srcK = gK + (size_t)(lt * 64 + lrow) * KVD2;
        const __half* srcV = gV + (size_t)(lt * 64 + lrow) * KVD2;
        uint32_t dK = sbase + buf * ATT_BUF_BYTES;
        uint32_t dV = dK + ATT_TILE_BYTES;
        cp16(dK + SW(lrow * 128 + lc * 16), srcK + lc * 8);
        cp16(dK + SW(lrow * 128 + (lc + 4) * 16), srcK + (lc + 4) * 8);
        cp16(dV + SW(lrow * 128 + lc * 16), srcV + lc * 8);
        cp16(dV + SW(lrow * 128 + (lc + 4) * 16), srcV + (lc + 4) * 8);
    };

    load_tiles(0, 0);
    asm volatile("cp.async.commit_group;\n");

    const int l15 = lane & 15;
    const int colh = (lane >> 4) << 4;
    const int r8 = (((lane >> 3) & 1) << 3) + (lane & 7);
    const int cpair = (lane >> 4) << 4;

    for (int lt = 0; lt < S_ / 64; lt++) {
        const int cur = lt & 1;
        if (lt + 1 < S_ / 64) load_tiles(1 - cur, lt + 1);
        asm volatile("cp.async.commit_group;\n");
        asm volatile("cp.async.wait_group 1;\n");
        __syncthreads();

        const uint32_t tbK = sbase + cur * ATT_BUF_BYTES;
        const uint32_t tbV = tbK + ATT_TILE_BYTES;

        #pragma unroll
        for (int half = 0; half < 2; half++) {
            float s[4][4];
            #pragma unroll
            for (int nt = 0; nt < 4; nt++)
                #pragma unroll
                for (int r = 0; r < 4; r++) s[nt][r] = 0.0f;

            #pragma unroll
            for (int np = 0; np < 2; np++) {
                #pragma unroll
                for (int kt = 0; kt < 4; kt++) {
                    const uint32_t inner =
                        (uint32_t)((half * 32 + np * 16 + l15) * 128 + kt * 32 + colh);
                    uint32_t th[4];
                    ldsm_x4(th, tbK + SW(inner));
                    mma2(s[2*np],   qf[0][kt], th[0], th[2]);
                    mma2(s[2*np+1], qf[0][kt], th[1], th[3]);
                    mma2(s[2*np],   qf[1][kt], th[0], th[2]);
                    mma2(s[2*np+1], qf[1][kt], th[1], th[3]);
                }
            }

            float mx0 = -1e30f, mx1 = -1e30f;
            #pragma unroll
            for (int nt = 0; nt < 4; nt++) {
                mx0 = fmaxf(mx0, fmaxf(s[nt][0], s[nt][1]));
                mx1 = fmaxf(mx1, fmaxf(s[nt][2], s[nt][3]));
            }
            mx0 = fmaxf(mx0, __shfl_xor_sync(0xffffffffu, mx0, 1));
            mx0 = fmaxf(mx0, __shfl_xor_sync(0xffffffffu, mx0, 2));
            mx1 = fmaxf(mx1, __shfl_xor_sync(0xffffffffu, mx1, 1));
            mx1 = fmaxf(mx1, __shfl_xor_sync(0xffffffffu, mx1, 2));
            const float mn0 = fmaxf(m0, mx0), mn1 = fmaxf(m1, mx1);
            const float sc0 = fexp2(m0 - mn0), sc1 = fexp2(m1 - mn1);
            m0 = mn0; m1 = mn1;
            l0 *= sc0; l1 *= sc1;
            #pragma unroll
            for (int nt = 0; nt < 8; nt++) {
                o[nt][0] *= sc0; o[nt][1] *= sc0; o[nt][2] *= sc1; o[nt][3] *= sc1;
            }
            #pragma unroll
            for (int nt = 0; nt < 4; nt++) {
                float p0 = fexp2(s[nt][0] - m0), p1 = fexp2(s[nt][1] - m0);
                float p2 = fexp2(s[nt][2] - m1), p3 = fexp2(s[nt][3] - m1);
                l0 += p0 + p1; l1 += p2 + p3;
                s[nt][0] = p0; s[nt][1] = p1; s[nt][2] = p2; s[nt][3] = p3;
            }

            uint32_t ph_[2][4], pl_[2][4];
            #pragma unroll
            for (int lk = 0; lk < 2; lk++) {
                ph_[lk][0] = packsplit_h(s[2*lk][0],   s[2*lk][1],   pl_[lk][0]);
                ph_[lk][1] = packsplit_h(s[2*lk][2],   s[2*lk][3],   pl_[lk][1]);
                ph_[lk][2] = packsplit_h(s[2*lk+1][0], s[2*lk+1][1], pl_[lk][2]);
                ph_[lk][3] = packsplit_h(s[2*lk+1][2], s[2*lk+1][3], pl_[lk][3]);
            }

            #pragma unroll
            for (int ntp = 0; ntp < 4; ntp++) {
                #pragma unroll
                for (int lk = 0; lk < 2; lk++) {
                    const uint32_t inner =
                        (uint32_t)((half * 32 + lk * 16 + r8) * 128 + ntp * 32 + cpair);
                    uint32_t vh[4];
                    ldsm_x4_t(vh, tbV + SW(inner));
                    mma2(o[2*ntp],   ph_[lk], vh[0], vh[1]);
                    mma2(o[2*ntp+1], ph_[lk], vh[2], vh[3]);
                    mma2(o[2*ntp],   pl_[lk], vh[0], vh[1]);
                    mma2(o[2*ntp+1], pl_[lk], vh[2], vh[3]);
                }
            }
        }
        __syncthreads();
    }

    l0 += __shfl_xor_sync(0xffffffffu, l0, 1);
    l0 += __shfl_xor_sync(0xffffffffu, l0, 2);
    l1 += __shfl_xor_sync(0xffffffffu, l1, 1);
    l1 += __shfl_xor_sync(0xffffffffu, l1, 2);
    const float inv0 = 1.0f / l0, inv1 = 1.0f / l1;

    // hi-only output (feeds 1-term O-projection)
    const size_t ro = ((size_t)(b * S_ + qrow + (lane >> 2))) * DMODEL + h * HD + (lane & 3) * 2;
    #pragma unroll
    for (int nt = 0; nt < 8; nt++) {
        __half2 h0, h1;
        h0.x = __float2half_rn(o[nt][0] * inv0); h0.y = __float2half_rn(o[nt][1] * inv0);
        h1.x = __float2half_rn(o[nt][2] * inv1); h1.y = __float2half_rn(o[nt][3] * inv1);
        *(__half2*)(AOh + ro + nt * 8)              = h0;
        *(__half2*)(AOh + ro + nt * 8 + 8 * DMODEL) = h1;
    }
}

// ---------------------------------------------------------------------------
// Launch
// ---------------------------------------------------------------------------
extern "C" void kernel_launch(void* const* d_in, const int* in_sizes, int n_in,
                              void* d_out, int out_size)
{
    const float* h_bsd = (const float*)d_in[0];
    const float* w_q   = (const float*)d_in[1];
    const float* w_k   = (const float*)d_in[2];
    const float* w_v   = (const float*)d_in[3];
    const float* w_o   = (const float*)d_in[4];
    float* out = (float*)d_out;

    __half *W, *Xh, *Xl, *Qh, *Ql, *KVh, *AOh;
    cudaGetSymbolAddress((void**)&W, g_W);
    cudaGetSymbolAddress((void**)&Xh, g_Xh);   cudaGetSymbolAddress((void**)&Xl, g_Xl);
    cudaGetSymbolAddress((void**)&Qh, g_Qh);   cudaGetSymbolAddress((void**)&Ql, g_Ql);
    cudaGetSymbolAddress((void**)&KVh, g_KVh);
    cudaGetSymbolAddress((void**)&AOh, g_AOh);

    static int attr_set = 0;
    if (!attr_set) {
        cudaFuncSetAttribute(flash_attn_mma,
                             cudaFuncAttributeMaxDynamicSharedMemorySize, ATT_SMEM);
        cudaFuncSetAttribute(gemm_split,
                             cudaFuncAttributeMaxDynamicSharedMemorySize, GEMM_SMEM);
        attr_set = 1;
    }

    cvt_w4<<<512, 256>>>(w_q, w_k, w_v, w_o, W);
    split2_f16<<<512, 256>>>(h_bsd, Xh, Xl, MROWS * DMODEL / 4);

    // Fused Q+KV projection over packed [Wq|Wk|Wv] (N = 3072, grid 12x32)
    gemm_split<<<dim3((DMODEL + KVD2) / TCN, MROWS / TCM), 512, GEMM_SMEM>>>(
        Xh, Xl, W, nullptr, Qh, Ql, KVh, MROWS, DMODEL, DMODEL);

    flash_attn_mma<<<dim3(S_ / 128, NQH, B_), 256, ATT_SMEM>>>(
        Qh, Ql, KVh, AOh);

    // O projection: 1-term (Al = nullptr), fp32 out
    gemm_split<<<dim3(DMODEL / TCN, MROWS / TCM), 512, GEMM_SMEM>>>(
        AOh, nullptr, W + NQW + 2 * NKW, out, nullptr, nullptr, nullptr,
        MROWS, DMODEL, DMODEL);
}

// round 17
// speedup vs baseline: 1.2623x; 1.0991x over previous
#include <cuda_runtime.h>
#include <cuda_fp16.h>
#include <math.h>
#include <stdint.h>

// Problem constants
#define B_      2
#define S_      2048
#define DMODEL  2048
#define NQH     32
#define NKVH    8
#define HD      64
#define KVDIM   (NKVH * HD)   // 512
#define KVD2    (2 * KVDIM)   // 1024 (K and V fused)
#define MROWS   (B_ * S_)     // 4096
#define NQW     (DMODEL * DMODEL)
#define NKW     (KVDIM * DMODEL)

// ---------------------------------------------------------------------------
// Scratch (__device__ globals)
// g_W rows: [Wq(2048) | Wk(512) | Wv(512) | Wo(2048)] x K=2048, fp16 hi-only
// ---------------------------------------------------------------------------
__device__ __half g_W  [2 * NQW + 2 * NKW];
__device__ __half g_Xh [MROWS * DMODEL], g_Xl [MROWS * DMODEL];
__device__ __half g_Qh [MROWS * DMODEL];
__device__ __half g_KVh[MROWS * KVD2];
__device__ __half g_AOh[MROWS * DMODEL];

// ---------------------------------------------------------------------------
// helpers
// ---------------------------------------------------------------------------
__device__ __forceinline__ uint32_t smem_u32(const void* p) {
    return (uint32_t)__cvta_generic_to_shared(p);
}

__device__ __forceinline__ uint32_t packsplit_h(float a, float b, uint32_t& lo) {
    __half ha = __float2half_rn(a), hb = __float2half_rn(b);
    __half la = __float2half_rn(a - __half2float(ha));
    __half lb = __float2half_rn(b - __half2float(hb));
    lo = ((uint32_t)__half_as_ushort(lb) << 16) | (uint32_t)__half_as_ushort(la);
    return ((uint32_t)__half_as_ushort(hb) << 16) | (uint32_t)__half_as_ushort(ha);
}

__device__ __forceinline__ float fexp2(float x) {
    float r;
    asm("ex2.approx.f32 %0, %1;" : "=f"(r) : "f"(x));
    return r;
}

__device__ __forceinline__ void mma2(float* c, const uint32_t* a, uint32_t b0, uint32_t b1) {
    asm volatile(
        "mma.sync.aligned.m16n8k16.row.col.f32.f16.f16.f32 "
        "{%0,%1,%2,%3}, {%4,%5,%6,%7}, {%8,%9}, {%0,%1,%2,%3};"
        : "+f"(c[0]), "+f"(c[1]), "+f"(c[2]), "+f"(c[3])
        : "r"(a[0]), "r"(a[1]), "r"(a[2]), "r"(a[3]), "r"(b0), "r"(b1));
}

__device__ __forceinline__ void ldsm_x4(uint32_t* r, uint32_t addr) {
    asm volatile("ldmatrix.sync.aligned.m8n8.x4.shared.b16 {%0,%1,%2,%3}, [%4];"
                 : "=r"(r[0]), "=r"(r[1]), "=r"(r[2]), "=r"(r[3]) : "r"(addr));
}
__device__ __forceinline__ void ldsm_x4_t(uint32_t* r, uint32_t addr) {
    asm volatile("ldmatrix.sync.aligned.m8n8.x4.trans.shared.b16 {%0,%1,%2,%3}, [%4];"
                 : "=r"(r[0]), "=r"(r[1]), "=r"(r[2]), "=r"(r[3]) : "r"(addr));
}

#define SW(a) ((a) ^ (((a) >> 3) & 0x70))

__device__ __forceinline__ void cp16(uint32_t d, const void* s) {
    asm volatile("cp.async.cg.shared.global [%0], [%1], 16;\n" :: "r"(d), "l"(s));
}

#define QSCALE 0.18033688011112042f   // 1/sqrt(64) * log2(e)

// ---------------------------------------------------------------------------
// Weight convert (hi-only fp16) into packed g_W
// ---------------------------------------------------------------------------
__global__ void cvt_w4(const float* __restrict__ wq, const float* __restrict__ wk,
                       const float* __restrict__ wv, const float* __restrict__ wo,
                       __half* __restrict__ W)
{
    const int total2 = (2 * NQW + 2 * NKW) / 2;
    for (int i = blockIdx.x * blockDim.x + threadIdx.x; i < total2;
         i += gridDim.x * blockDim.x) {
        const int idx = i * 2;
        const float* src; int off;
        if (idx < NQW)                 { src = wq; off = idx; }
        else if (idx < NQW + NKW)      { src = wk; off = idx - NQW; }
        else if (idx < NQW + 2 * NKW)  { src = wv; off = idx - NQW - NKW; }
        else                           { src = wo; off = idx - NQW - 2 * NKW; }
        float2 v = *(const float2*)(src + off);
        __half2 h; h.x = __float2half_rn(v.x); h.y = __float2half_rn(v.y);
        *(__half2*)(W + idx) = h;
    }
}

// ---------------------------------------------------------------------------
// X: fp32 -> (hi, lo) fp16 buffers.
// ---------------------------------------------------------------------------
__global__ void split2_f16(const float* __restrict__ X,
                           __half* __restrict__ Yh, __half* __restrict__ Yl, int total4)
{
    for (int i = blockIdx.x * blockDim.x + threadIdx.x; i < total4;
         i += gridDim.x * blockDim.x) {
        const int idx = i * 4;
        float4 x = *(const float4*)(X + idx);
        uint32_t lo0, lo1;
        uint32_t hi0 = packsplit_h(x.x, x.y, lo0);
        uint32_t hi1 = packsplit_h(x.z, x.w, lo1);
        *(uint2*)(Yh + idx) = make_uint2(hi0, hi1);
        *(uint2*)(Yl + idx) = make_uint2(lo0, lo1);
    }
}

// ---------------------------------------------------------------------------
// Split-precision GEMM (r15 proven config):
//   acc = (Ah [+ Al]) * Bh^T     (Al == nullptr -> 1-term)
// CTA 128x256, 512 threads, 16 warps (4M x 4N) at 32x64, TCK=64, 2-stage.
// Output: C != 0 -> fp32 (stride ostride); else fp16 hi * cscale (stride ostride).
// ---------------------------------------------------------------------------
#define TCM 128
#define TCN 256
#define TCK 64
#define GA_AL 16384
#define GA_BH 32768
#define STAGE_BYTES 65536
#define GEMM_SMEM (2 * STAGE_BYTES)    // 131072

__global__ void __launch_bounds__(512, 1) gemm_split(
    const __half* __restrict__ Ah, const __half* __restrict__ Al,
    const __half* __restrict__ Bh,
    float* __restrict__ C, __half* __restrict__ Chi,
    float cscale, int ostride, int Kk)
{
    extern __shared__ __align__(1024) char sm[];
    const uint32_t sb = smem_u32(sm);

    const int tid  = threadIdx.x;
    const int lane = tid & 31;
    const int w    = tid >> 5;
    const int wm   = (w & 3) * 32;
    const int wn   = (w >> 2) * 64;
    const int bm   = blockIdx.y * TCM;
    const int bn   = blockIdx.x * TCN;
    const bool two_term = (Al != nullptr);

    float acc[2][8][4];
    #pragma unroll
    for (int mi = 0; mi < 2; mi++)
        #pragma unroll
        for (int nt = 0; nt < 8; nt++)
            #pragma unroll
            for (int r = 0; r < 4; r++) acc[mi][nt][r] = 0.0f;

    const int arow = tid >> 2, ach = (tid & 3) * 2;
    const int brow = tid >> 1, bch = (tid & 1) * 4;
    const __half* gAh = Ah + (size_t)(bm + arow) * Kk + ach * 8;
    const __half* gAl = two_term ? (Al + (size_t)(bm + arow) * Kk + ach * 8) : gAh;
    const __half* gBh = Bh + (size_t)(bn + brow) * Kk + bch * 8;

    auto load_stage = [&](int buf, int kt) {
        const uint32_t st = sb + buf * STAGE_BYTES;
        const int k0 = kt * TCK;
        #pragma unroll
        for (int j = 0; j < 2; j++) {
            const uint32_t d = SW((uint32_t)(arow * 128 + (ach + j) * 16));
            cp16(st + d, gAh + k0 + j * 8);
            if (two_term) cp16(st + GA_AL + d, gAl + k0 + j * 8);
        }
        #pragma unroll
        for (int j = 0; j < 4; j++) {
            const uint32_t d = SW((uint32_t)(brow * 128 + (bch + j) * 16));
            cp16(st + GA_BH + d, gBh + k0 + j * 8);
        }
    };

    const int NT = Kk / TCK;
    load_stage(0, 0);
    asm volatile("cp.async.commit_group;\n");

    const int l15 = lane & 15;
    const int colh = (lane >> 4) << 4;

    for (int kt = 0; kt < NT; kt++) {
        const int cur = kt & 1;
        if (kt + 1 < NT) {
            load_stage(1 - cur, kt + 1);
            asm volatile("cp.async.commit_group;\n");
            asm volatile("cp.async.wait_group 1;\n");
        } else {
            asm volatile("cp.async.wait_group 0;\n");
        }
        __syncthreads();

        const uint32_t st = sb + cur * STAGE_BYTES;

        #pragma unroll
        for (int kk = 0; kk < 4; kk++) {
            const uint32_t colb = (uint32_t)(kk * 32 + colh);
            uint32_t ah[2][4], al[2][4];
            #pragma unroll
            for (int mi = 0; mi < 2; mi++) {
                const uint32_t off = SW((uint32_t)((wm + mi * 16 + l15) * 128) + colb);
                ldsm_x4(ah[mi], st + off);
                if (two_term) ldsm_x4(al[mi], st + GA_AL + off);
            }
            #pragma unroll
            for (int np = 0; np < 4; np++) {
                const uint32_t offb = SW((uint32_t)((wn + np * 16 + l15) * 128) + colb);
                uint32_t t[4];
                ldsm_x4(t, st + GA_BH + offb);
                mma2(acc[0][2*np],   ah[0], t[0], t[2]);
                mma2(acc[0][2*np+1], ah[0], t[1], t[3]);
                mma2(acc[1][2*np],   ah[1], t[0], t[2]);
                mma2(acc[1][2*np+1], ah[1], t[1], t[3]);
                if (two_term) {
                    mma2(acc[0][2*np],   al[0], t[0], t[2]);
                    mma2(acc[0][2*np+1], al[0], t[1], t[3]);
                    mma2(acc[1][2*np],   al[1], t[0], t[2]);
                    mma2(acc[1][2*np+1], al[1], t[1], t[3]);
                }
            }
        }
        __syncthreads();
    }

    if (C) {
        #pragma unroll
        for (int mi = 0; mi < 2; mi++) {
            const int r0 = bm + wm + mi * 16 + (lane >> 2);
            #pragma unroll
            for (int nt = 0; nt < 8; nt++) {
                const int c0 = bn + wn + nt * 8 + 2 * (lane & 3);
                *(float2*)(C + (size_t)r0 * ostride + c0)       = make_float2(acc[mi][nt][0], acc[mi][nt][1]);
                *(float2*)(C + (size_t)(r0 + 8) * ostride + c0) = make_float2(acc[mi][nt][2], acc[mi][nt][3]);
            }
        }
    } else {
        #pragma unroll
        for (int mi = 0; mi < 2; mi++) {
            const int r0 = bm + wm + mi * 16 + (lane >> 2);
            #pragma unroll
            for (int nt = 0; nt < 8; nt++) {
                const int c0 = bn + wn + nt * 8 + 2 * (lane & 3);
                __half2 h0, h1;
                h0.x = __float2half_rn(acc[mi][nt][0] * cscale);
                h0.y = __float2half_rn(acc[mi][nt][1] * cscale);
                h1.x = __float2half_rn(acc[mi][nt][2] * cscale);
                h1.y = __float2half_rn(acc[mi][nt][3] * cscale);
                *(__half2*)(Chi + (size_t)r0 * ostride + c0)       = h0;
                *(__half2*)(Chi + (size_t)(r0 + 8) * ostride + c0) = h1;
            }
        }
    }
}

// ---------------------------------------------------------------------------
// fp16 flash attention: Q hi-only (1-term QK), P 2-term PV, halved tiles,
// log2-domain softmax, 2 CTAs/SM.
// ---------------------------------------------------------------------------
#define ATT_TILE_BYTES 8192
#define ATT_BUF_BYTES  (2 * ATT_TILE_BYTES)
#define ATT_SMEM       (2 * ATT_BUF_BYTES)   // 32768

__global__ void __launch_bounds__(256, 2) flash_attn_mma(
    const __half* __restrict__ Qh,
    const __half* __restrict__ KVh,
    __half* __restrict__ AOh)
{
    extern __shared__ __half smem[];
    const uint32_t sbase = smem_u32(smem);

    const int b    = blockIdx.z;
    const int h    = blockIdx.y;
    const int kvh  = h >> 2;
    const int tid  = threadIdx.x;
    const int lane = tid & 31;
    const int w    = tid >> 5;
    const int qrow = blockIdx.x * 128 + w * 16;

    uint32_t qf[4][4];
    {
        const size_t base = ((size_t)(b * S_ + qrow + (lane >> 2))) * DMODEL + h * HD + (lane & 3) * 2;
        #pragma unroll
        for (int kt = 0; kt < 4; kt++) {
            const size_t c = base + kt * 16;
            qf[kt][0] = *(const uint32_t*)(Qh + c);
            qf[kt][1] = *(const uint32_t*)(Qh + c + 8 * DMODEL);
            qf[kt][2] = *(const uint32_t*)(Qh + c + 8);
            qf[kt][3] = *(const uint32_t*)(Qh + c + 8 * DMODEL + 8);
        }
    }

    float o[8][4];
    #pragma unroll
    for (int nt = 0; nt < 8; nt++)
        #pragma unroll
        for (int r = 0; r < 4; r++) o[nt][r] = 0.0f;
    float m0 = -1e30f, m1 = -1e30f, l0 = 0.0f, l1 = 0.0f;

    const size_t kvbase = (size_t)b * S_ * KVD2 + kvh * HD;
    const __half* gK = KVh + kvbase;
    const __half* gV = KVh + kvbase + KVDIM;
    const int lrow = tid >> 2;
    const int lc   = tid & 3;

    auto load_tiles = [&](int buf, int lt) {
        const __half* srcK = gK + (size_t)(lt * 64 + lrow) * KVD2;
        const __half* srcV = gV + (size_t)(lt * 64 + lrow) * KVD2;
        uint32_t dK = sbase + buf * ATT_BUF_BYTES;
        uint32_t dV = dK + ATT_TILE_BYTES;
        cp16(dK + SW(lrow * 128 + lc * 16), srcK + lc * 8);
        cp16(dK + SW(lrow * 128 + (lc + 4) * 16), srcK + (lc + 4) * 8);
        cp16(dV + SW(lrow * 128 + lc * 16), srcV + lc * 8);
        cp16(dV + SW(lrow * 128 + (lc + 4) * 16), srcV + (lc + 4) * 8);
    };

    load_tiles(0, 0);
    asm volatile("cp.async.commit_group;\n");

    const int l15 = lane & 15;
    const int colh = (lane >> 4) << 4;
    const int r8 = (((lane >> 3) & 1) << 3) + (lane & 7);
    const int cpair = (lane >> 4) << 4;

    for (int lt = 0; lt < S_ / 64; lt++) {
        const int cur = lt & 1;
        if (lt + 1 < S_ / 64) load_tiles(1 - cur, lt + 1);
        asm volatile("cp.async.commit_group;\n");
        asm volatile("cp.async.wait_group 1;\n");
        __syncthreads();

        const uint32_t tbK = sbase + cur * ATT_BUF_BYTES;
        const uint32_t tbV = tbK + ATT_TILE_BYTES;

        #pragma unroll
        for (int half = 0; half < 2; half++) {
            float s[4][4];
            #pragma unroll
            for (int nt = 0; nt < 4; nt++)
                #pragma unroll
                for (int r = 0; r < 4; r++) s[nt][r] = 0.0f;

            // ---- S-half = Qh Kh^T (1-term)
            #pragma unroll
            for (int np = 0; np < 2; np++) {
                #pragma unroll
                for (int kt = 0; kt < 4; kt++) {
                    const uint32_t inner =
                        (uint32_t)((half * 32 + np * 16 + l15) * 128 + kt * 32 + colh);
                    uint32_t th[4];
                    ldsm_x4(th, tbK + SW(inner));
                    mma2(s[2*np],   qf[kt], th[0], th[2]);
                    mma2(s[2*np+1], qf[kt], th[1], th[3]);
                }
            }

            // ---- online softmax partial update
            float mx0 = -1e30f, mx1 = -1e30f;
            #pragma unroll
            for (int nt = 0; nt < 4; nt++) {
                mx0 = fmaxf(mx0, fmaxf(s[nt][0], s[nt][1]));
                mx1 = fmaxf(mx1, fmaxf(s[nt][2], s[nt][3]));
            }
            mx0 = fmaxf(mx0, __shfl_xor_sync(0xffffffffu, mx0, 1));
            mx0 = fmaxf(mx0, __shfl_xor_sync(0xffffffffu, mx0, 2));
            mx1 = fmaxf(mx1, __shfl_xor_sync(0xffffffffu, mx1, 1));
            mx1 = fmaxf(mx1, __shfl_xor_sync(0xffffffffu, mx1, 2));
            const float mn0 = fmaxf(m0, mx0), mn1 = fmaxf(m1, mx1);
            const float sc0 = fexp2(m0 - mn0), sc1 = fexp2(m1 - mn1);
            m0 = mn0; m1 = mn1;
            l0 *= sc0; l1 *= sc1;
            #pragma unroll
            for (int nt = 0; nt < 8; nt++) {
                o[nt][0] *= sc0; o[nt][1] *= sc0; o[nt][2] *= sc1; o[nt][3] *= sc1;
            }
            #pragma unroll
            for (int nt = 0; nt < 4; nt++) {
                float p0 = fexp2(s[nt][0] - m0), p1 = fexp2(s[nt][1] - m0);
                float p2 = fexp2(s[nt][2] - m1), p3 = fexp2(s[nt][3] - m1);
                l0 += p0 + p1; l1 += p2 + p3;
                s[nt][0] = p0; s[nt][1] = p1; s[nt][2] = p2; s[nt][3] = p3;
            }

            uint32_t ph_[2][4], pl_[2][4];
            #pragma unroll
            for (int lk = 0; lk < 2; lk++) {
                ph_[lk][0] = packsplit_h(s[2*lk][0],   s[2*lk][1],   pl_[lk][0]);
                ph_[lk][1] = packsplit_h(s[2*lk][2],   s[2*lk][3],   pl_[lk][1]);
                ph_[lk][2] = packsplit_h(s[2*lk+1][0], s[2*lk+1][1], pl_[lk][2]);
                ph_[lk][3] = packsplit_h(s[2*lk+1][2], s[2*lk+1][3], pl_[lk][3]);
            }

            // ---- O += (Ph+Pl) Vh
            #pragma unroll
            for (int ntp = 0; ntp < 4; ntp++) {
                #pragma unroll
                for (int lk = 0; lk < 2; lk++) {
                    const uint32_t inner =
                        (uint32_t)((half * 32 + lk * 16 + r8) * 128 + ntp * 32 + cpair);
                    uint32_t vh[4];
                    ldsm_x4_t(vh, tbV + SW(inner));
                    mma2(o[2*ntp],   ph_[lk], vh[0], vh[1]);
                    mma2(o[2*ntp+1], ph_[lk], vh[2], vh[3]);
                    mma2(o[2*ntp],   pl_[lk], vh[0], vh[1]);
                    mma2(o[2*ntp+1], pl_[lk], vh[2], vh[3]);
                }
            }
        }
        __syncthreads();
    }

    l0 += __shfl_xor_sync(0xffffffffu, l0, 1);
    l0 += __shfl_xor_sync(0xffffffffu, l0, 2);
    l1 += __shfl_xor_sync(0xffffffffu, l1, 1);
    l1 += __shfl_xor_sync(0xffffffffu, l1, 2);
    const float inv0 = 1.0f / l0, inv1 = 1.0f / l1;

    const size_t ro = ((size_t)(b * S_ + qrow + (lane >> 2))) * DMODEL + h * HD + (lane & 3) * 2;
    #pragma unroll
    for (int nt = 0; nt < 8; nt++) {
        __half2 h0, h1;
        h0.x = __float2half_rn(o[nt][0] * inv0); h0.y = __float2half_rn(o[nt][1] * inv0);
        h1.x = __float2half_rn(o[nt][2] * inv1); h1.y = __float2half_rn(o[nt][3] * inv1);
        *(__half2*)(AOh + ro + nt * 8)              = h0;
        *(__half2*)(AOh + ro + nt * 8 + 8 * DMODEL) = h1;
    }
}

// ---------------------------------------------------------------------------
// Launch
// ---------------------------------------------------------------------------
extern "C" void kernel_launch(void* const* d_in, const int* in_sizes, int n_in,
                              void* d_out, int out_size)
{
    const float* h_bsd = (const float*)d_in[0];
    const float* w_q   = (const float*)d_in[1];
    const float* w_k   = (const float*)d_in[2];
    const float* w_v   = (const float*)d_in[3];
    const float* w_o   = (const float*)d_in[4];
    float* out = (float*)d_out;

    __half *W, *Xh, *Xl, *Qh, *KVh, *AOh;
    cudaGetSymbolAddress((void**)&W, g_W);
    cudaGetSymbolAddress((void**)&Xh, g_Xh);   cudaGetSymbolAddress((void**)&Xl, g_Xl);
    cudaGetSymbolAddress((void**)&Qh, g_Qh);
    cudaGetSymbolAddress((void**)&KVh, g_KVh);
    cudaGetSymbolAddress((void**)&AOh, g_AOh);

    static int attr_set = 0;
    if (!attr_set) {
        cudaFuncSetAttribute(flash_attn_mma,
                             cudaFuncAttributeMaxDynamicSharedMemorySize, ATT_SMEM);
        cudaFuncSetAttribute(gemm_split,
                             cudaFuncAttributeMaxDynamicSharedMemorySize, GEMM_SMEM);
        attr_set = 1;
    }

    cvt_w4<<<512, 256>>>(w_q, w_k, w_v, w_o, W);
    split2_f16<<<512, 256>>>(h_bsd, Xh, Xl, MROWS * DMODEL / 4);

    // Q projection: 2-term compute, hi-only scaled output
    gemm_split<<<dim3(DMODEL / TCN, MROWS / TCM), 512, GEMM_SMEM>>>(
        Xh, Xl, W, nullptr, Qh, QSCALE, DMODEL, DMODEL);
    // KV projection: 2-term compute, hi-only output
    gemm_split<<<dim3(KVD2 / TCN, MROWS / TCM), 512, GEMM_SMEM>>>(
        Xh, Xl, W + NQW, nullptr, KVh, 1.0f, KVD2, DMODEL);

    flash_attn_mma<<<dim3(S_ / 128, NQH, B_), 256, ATT_SMEM>>>(Qh, KVh, AOh);

    // O projection: 1-term, fp32 out
    gemm_split<<<dim3(DMODEL / TCN, MROWS / TCM), 512, GEMM_SMEM>>>(
        AOh, nullptr, W + NQW + 2 * NKW, out, nullptr, 1.0f, DMODEL, DMODEL);
}